// round 6
// baseline (speedup 1.0000x reference)
#include <cuda_runtime.h>
#include <cstdint>

// ---------------------------------------------------------------------------
// ST-LSTM persistent kernel, fp32 f32x2. Round 6:
//  - W_s rows padded to 24 floats; thread owns 10 CONTIGUOUS cols =>
//    weight fetch is 2xLDS.128+1xLDS.64 (3 LDS/k-row, was 5)
//  - under-barrier x-GEMM shrunk to 8 rows (rows 0-7 folded into main GEMM)
//  - 512 thr/CTA, flag-array grid barrier, SMEM weights, local gates/c-ring
// 128 CTAs. CTA owns 4 h-cols (20 z-cols), full K=1280.
// ---------------------------------------------------------------------------

#define NCTA 128
#define NTHR 512

constexpr int Bb = 64, Ii = 256, Hh = 512;
constexpr int G5H   = 2560;
constexpr int STEPS = 1600;
constexpr int HB    = Hh * Bb;     // 32768
constexpr int XB    = Ii * Bb;     // 16384
constexpr int BH    = Bb * Hh;
constexpr int NPC   = 20;          // z-cols per CTA
constexpr int KSL   = 16;          // k-slices
constexpr int RS    = 1296;        // reduce row stride (floats)
constexpr int WSTR  = 24;          // W_s row stride (floats), both halves 16B-aligned

constexpr int W_OFF = 0;                    // 1280*24 = 30720
constexpr int R_OFF = 30720;                // 16*1296 = 20736
constexpr int C_OFF = R_OFF + KSL * RS;     // 25*256  = 6400
constexpr int SM_FLOATS  = C_OFF + 25 * 256;           // 57856
constexpr int SMEM_BYTES = SM_FLOATS * 4;              // 231,424 B (<= 227KB cap)

// --------------------------- device scratch --------------------------------
__device__ float    g_xT[(size_t)STEPS * XB];  // x transposed [tj][i][b]
__device__ float    g_hT[32 * HB];             // h ring [slot][n][b]
__device__ unsigned g_flags[NCTA * 8];         // padded arrival flags
__device__ unsigned g_cnt = 0;                 // init barrier (one-shot, self-reset)
__device__ unsigned g_gen = 0;

// --------------------------- helpers ---------------------------------------
__device__ __forceinline__ void init_barrier() {   // counter/gen style, used once
    __syncthreads();
    if (threadIdx.x == 0) {
        unsigned gen = *(volatile unsigned*)&g_gen;
        __threadfence();
        unsigned rank = atomicAdd(&g_cnt, 1u);
        if (rank == NCTA - 1) {
            g_cnt = 0;
            __threadfence();
            *(volatile unsigned*)&g_gen = gen + 1u;
        } else {
            while (*(volatile unsigned*)&g_gen == gen) { __nanosleep(64); }
        }
        __threadfence();
    }
    __syncthreads();
}

__device__ __forceinline__ void bar_arrive(int cta, int t, unsigned k) {
    __syncthreads();
    __threadfence();
    if (t == 0) *(volatile unsigned*)&g_flags[cta * 8] = k;
}
__device__ __forceinline__ void bar_wait(int t, unsigned k) {
    if (t < NCTA) {
        const unsigned* p = &g_flags[t * 8];
        unsigned v;
        asm volatile("ld.global.cg.u32 %0, [%1];" : "=r"(v) : "l"(p));
        while ((int)(v - k) < 0) {
            __nanosleep(32);
            asm volatile("ld.global.cg.u32 %0, [%1];" : "=r"(v) : "l"(p));
        }
    }
    __syncthreads();
    __threadfence();
}

__device__ __forceinline__ float fexp(float x) {
    float r;
    asm("ex2.approx.f32 %0, %1;" : "=f"(r) : "f"(x * 1.4426950408889634f));
    return r;
}
__device__ __forceinline__ float frcp(float x) {
    float r;
    asm("rcp.approx.f32 %0, %1;" : "=f"(r) : "f"(x));
    return r;
}
__device__ __forceinline__ float fsig(float x)  { return frcp(1.0f + fexp(-x)); }
__device__ __forceinline__ float ftanh(float x) { return 1.0f - 2.0f * frcp(1.0f + fexp(2.0f * x)); }

// --------------------------- kernel ----------------------------------------
__global__ void __launch_bounds__(NTHR, 1)
stlstm_kernel(const float* __restrict__ x,
              const float* __restrict__ Wx,
              const float* __restrict__ Whs,
              const float* __restrict__ Wht,
              const float* __restrict__ bias,
              float* __restrict__ out)
{
    extern __shared__ float sm[];
    float* W_s = sm + W_OFF;    // [1280][24]: cols 0-9 -> local 0-9, 12-21 -> local 10-19
    float* red = sm + R_OFF;
    float* c_s = sm + C_OFF;

    const int t   = threadIdx.x;
    const int cta = blockIdx.x;
    const int nt  = cta;

    // -------- pre-barrier init: flags, x transpose, ring zero, weights ------
    if (t == 0) *(volatile unsigned*)&g_flags[cta * 8] = 0u;
    {
        float* tmp = red;                      // 20736 floats >= 64*257
        for (int tj = cta; tj < STEPS; tj += NCTA) {
            const float* xsrc = x + (size_t)tj * (Bb * Ii);
            for (int idx = t; idx < Bb * Ii; idx += NTHR) {
                int bb = idx >> 8, ii = idx & 255;
                tmp[bb * 257 + ii] = xsrc[idx];
            }
            __syncthreads();
            float* xdst = g_xT + (size_t)tj * XB;
            for (int idx = t; idx < Bb * Ii; idx += NTHR) {
                int ii = idx >> 6, bb = idx & 63;
                xdst[idx] = tmp[bb * 257 + ii];
            }
            __syncthreads();
        }
    }
    {   // zero h-ring slots 7..31 (all early reads land there)
        float* z = g_hT + 7 * HB;
        for (int idx = cta * NTHR + t; idx < 25 * HB; idx += NCTA * NTHR) z[idx] = 0.0f;
    }
    for (int idx = t; idx < 25 * 256; idx += NTHR) c_s[idx] = 0.0f;

    // weights: local col c in [0,20); SMEM slot c<10 ? c : c+2 (halves 16B-aligned)
    for (int idx = t; idx < 1280 * NPC; idx += NTHR) {
        int k = idx / NPC, c = idx % NPC;
        int g = c >> 2, hc = c & 3;
        int col = g * Hh + nt * 4 + hc;
        float w;
        if (k < Hh)            w = Whs[(size_t)k * G5H + col];
        else if (k < 2 * Hh)   w = Wht[(size_t)(k - Hh) * G5H + col];
        else                   w = Wx [(size_t)(k - 2 * Hh) * G5H + col];
        W_s[k * WSTR + (c < 10 ? c : c + 2)] = w;
    }

    float ba[5];
    {
        int hc = t & 3;
        #pragma unroll
        for (int g = 0; g < 5; ++g) ba[g] = bias[g * Hh + nt * 4 + hc];
    }

    init_barrier();   // x ready, rings zeroed, flags zeroed

    // GEMM mapping: thread = (ng, mg, ks); ks warp-uniform.
    // Thread tile: 4 b-rows x 10 contiguous local cols x 80 k-rows (64 h + 16 x).
    const int ng   = t & 1;
    const int mg   = (t >> 1) & 15;
    const int ks   = t >> 5;
    const int b_lo = mg * 4;
    const int ng12 = ng * 12;            // SMEM half offset (floats)
    const int ng10 = ng * 10;            // red half offset
    const int khW  = ks * 64;            // W row base, h part
    const int kxW  = 1024 + ks * 16;     // W row base, x part

    const int bg  = t >> 2;              // gate phase (t < 256)
    const int hcg = t & 3;

    unsigned long long acc[4][5];
    float4 bufA[4], bufB[4];

#define ZERO_ACC()                                                            \
    {  _Pragma("unroll")                                                      \
       for (int i = 0; i < 4; ++i)                                            \
           _Pragma("unroll")                                                  \
           for (int g = 0; g < 5; ++g) acc[i][g] = 0ull; }

#define LOADBLK(BUF, PA, BLK)                                                 \
    {  _Pragma("unroll")                                                      \
       for (int u = 0; u < 4; ++u)                                            \
           BUF[u] = __ldcg((const float4*)((PA) + ((BLK) * 4 + u) * 64));     \
    }

#define FMABLK(BUF, KWB, BLK)                                                 \
    {  _Pragma("unroll")                                                      \
       for (int u = 0; u < 4; ++u) {                                          \
           const float* wr = W_s + ((KWB) + (BLK) * 4 + u) * WSTR + ng12;     \
           ulonglong2 wa = *(const ulonglong2*)(wr);                          \
           ulonglong2 wb = *(const ulonglong2*)(wr + 4);                      \
           unsigned long long w4 = *(const unsigned long long*)(wr + 8);      \
           float av[4] = {BUF[u].x, BUF[u].y, BUF[u].z, BUF[u].w};            \
           _Pragma("unroll")                                                  \
           for (int i = 0; i < 4; ++i) {                                      \
               unsigned long long aa;                                         \
               asm("mov.b64 %0, {%1, %1};" : "=l"(aa) : "f"(av[i]));          \
               asm("fma.rn.f32x2 %0, %1, %2, %0;" : "+l"(acc[i][0]) : "l"(aa), "l"(wa.x)); \
               asm("fma.rn.f32x2 %0, %1, %2, %0;" : "+l"(acc[i][1]) : "l"(aa), "l"(wa.y)); \
               asm("fma.rn.f32x2 %0, %1, %2, %0;" : "+l"(acc[i][2]) : "l"(aa), "l"(wb.x)); \
               asm("fma.rn.f32x2 %0, %1, %2, %0;" : "+l"(acc[i][3]) : "l"(aa), "l"(wb.y)); \
               asm("fma.rn.f32x2 %0, %1, %2, %0;" : "+l"(acc[i][4]) : "l"(aa), "l"(w4)); \
           } } }

    // under-barrier x tail: rows 8..15 of this thread's x slice
#define XGEMM_TAIL(S)                                                         \
    {  const float* pX = g_xT + (size_t)(S) * XB + (ks * 16) * 64 + b_lo;     \
       LOADBLK(bufA, pX, 2)                                                   \
       LOADBLK(bufB, pX, 3)                                                   \
       FMABLK(bufA, kxW, 2)                                                   \
       FMABLK(bufB, kxW, 3) }

    // prologue: x tail of step 0
    ZERO_ACC()
    XGEMM_TAIL(0)

    // ---------------- main sequential loop ----------------------------------
    for (int step = 0; step < STEPS; ++step) {

        // ---- h-part GEMM (16 blocks) + x rows 0..7 (2 blocks) ----
        {
            const float* h1  = g_hT + ((step - 1)  & 31) * HB;
            const float* h25 = g_hT + ((step - 25) & 31) * HB;
            const float* pH  = ((ks < 8) ? (h1 + khW * 64)
                                         : (h25 + (khW - 512) * 64)) + b_lo;
            const float* pX  = g_xT + (size_t)step * XB + (ks * 16) * 64 + b_lo;
            LOADBLK(bufA, pH, 0)
            #pragma unroll 1
            for (int blk = 0; blk < 16; blk += 2) {
                LOADBLK(bufB, pH, blk + 1)
                FMABLK(bufA, khW, blk)
                if (blk + 2 < 16) LOADBLK(bufA, pH, blk + 2)
                else              LOADBLK(bufA, pX, 0)
                FMABLK(bufB, khW, blk + 1)
            }
            LOADBLK(bufB, pX, 1)
            FMABLK(bufA, kxW, 0)
            FMABLK(bufB, kxW, 1)
        }

        __syncthreads();   // red buffer free (previous gate phase done)

        // ---- store partials: thread's 10 contiguous local cols ----
        {
            float* rrow = red + ks * RS + ng10;
            #pragma unroll
            for (int i = 0; i < 4; ++i) {
                float* rb = rrow + (b_lo + i) * NPC;
                #pragma unroll
                for (int p = 0; p < 5; ++p)
                    *(float2*)(rb + 2 * p) = *(float2*)&acc[i][p];
            }
        }
        __syncthreads();

        // ---- reduce + gates (local, threads 0..255) ----
        if (t < 256) {
            float z[5];
            #pragma unroll
            for (int g = 0; g < 5; ++g) {
                float s = ba[g];
                const float* rp = red + bg * NPC + g * 4 + hcg;
                #pragma unroll
                for (int q = 0; q < KSL; ++q) s += rp[q * RS];
                z[g] = s;
            }
            float cs = c_s[((step + 24) % 25) * 256 + t];
            float ct = c_s[(step % 25) * 256 + t];
            float cc = fsig(z[0]) * ftanh(z[3]) + fsig(z[1]) * cs + fsig(z[2]) * ct;
            float hv = fsig(z[4]) * ftanh(cc);
            c_s[(step % 25) * 256 + t] = cc;

            int n = nt * 4 + hcg;
            out[(size_t)step * BH + bg * Hh + n] = hv;
            g_hT[(step & 31) * HB + n * 64 + bg] = hv;
        }

        // ---- arrive, hide barrier behind next step's x tail (8 rows) ----
        bar_arrive(cta, t, (unsigned)(step + 1));
        if (step + 1 < STEPS) {
            ZERO_ACC()
            XGEMM_TAIL(step + 1)
            bar_wait(t, (unsigned)(step + 1));
        }
    }
#undef ZERO_ACC
#undef LOADBLK
#undef FMABLK
#undef XGEMM_TAIL
}

// --------------------------- launch ----------------------------------------
extern "C" void kernel_launch(void* const* d_in, const int* in_sizes, int n_in,
                              void* d_out, int out_size)
{
    const float* x    = (const float*)d_in[0];
    const float* Wx   = (const float*)d_in[1];
    const float* Whs  = (const float*)d_in[2];
    const float* Wht  = (const float*)d_in[3];
    const float* bias = (const float*)d_in[4];
    float*       out  = (float*)d_out;

    cudaFuncSetAttribute(stlstm_kernel,
                         cudaFuncAttributeMaxDynamicSharedMemorySize, SMEM_BYTES);
    stlstm_kernel<<<NCTA, NTHR, SMEM_BYTES>>>(x, Wx, Whs, Wht, bias, out);
}

// round 8
// speedup vs baseline: 1.0603x; 1.0603x over previous
#include <cuda_runtime.h>
#include <cstdint>

// ---------------------------------------------------------------------------
// ST-LSTM persistent kernel, fp32 f32x2. Round 7 = R5 structure (best) +
//  (a) contiguous-col weight layout: 3 LDS/k-row (2xLDS.128+1xLDS.64)
//  (b) split k-slice reduction across both 256-thread halves
// 128 CTAs x 512 thr. CTA owns 4 h-cols (20 z-cols), full K=1280.
// Flag-array grid barrier; whole x-part GEMM hidden under the barrier.
// ---------------------------------------------------------------------------

#define NCTA 128
#define NTHR 512

constexpr int Bb = 64, Ii = 256, Hh = 512;
constexpr int G5H   = 2560;
constexpr int STEPS = 1600;
constexpr int HB    = Hh * Bb;     // 32768
constexpr int XB    = Ii * Bb;     // 16384
constexpr int BH    = Bb * Hh;
constexpr int NPC   = 20;          // z-cols per CTA
constexpr int KSL   = 16;          // k-slices
constexpr int RS    = 1296;        // reduce row stride (floats)
constexpr int WSTR  = 24;          // W_s row stride; halves at +0 / +12 (16B-aligned)

constexpr int W_OFF = 0;                    // 1280*24 = 30720
constexpr int R_OFF = 30720;                // 16*1296 = 20736
constexpr int C_OFF = R_OFF + KSL * RS;     // 25*256  = 6400
constexpr int SM_FLOATS  = C_OFF + 25 * 256;           // 57856
constexpr int SMEM_BYTES = SM_FLOATS * 4;              // 231,424 B

// --------------------------- device scratch --------------------------------
__device__ float    g_xT[(size_t)STEPS * XB];  // x transposed [tj][i][b]
__device__ float    g_hT[32 * HB];             // h ring [slot][n][b]
__device__ unsigned g_flags[NCTA * 8];         // padded arrival flags
__device__ unsigned g_cnt = 0;                 // init barrier (one-shot, self-reset)
__device__ unsigned g_gen = 0;

// --------------------------- helpers ---------------------------------------
__device__ __forceinline__ void init_barrier() {
    __syncthreads();
    if (threadIdx.x == 0) {
        unsigned gen = *(volatile unsigned*)&g_gen;
        __threadfence();
        unsigned rank = atomicAdd(&g_cnt, 1u);
        if (rank == NCTA - 1) {
            g_cnt = 0;
            __threadfence();
            *(volatile unsigned*)&g_gen = gen + 1u;
        } else {
            while (*(volatile unsigned*)&g_gen == gen) { __nanosleep(64); }
        }
        __threadfence();
    }
    __syncthreads();
}

__device__ __forceinline__ void bar_arrive(int cta, int t, unsigned k) {
    __syncthreads();
    __threadfence();
    if (t == 0) *(volatile unsigned*)&g_flags[cta * 8] = k;
}
__device__ __forceinline__ void bar_wait(int t, unsigned k) {
    if (t < NCTA) {
        const unsigned* p = &g_flags[t * 8];
        unsigned v;
        asm volatile("ld.global.cg.u32 %0, [%1];" : "=r"(v) : "l"(p));
        while ((int)(v - k) < 0) {
            __nanosleep(32);
            asm volatile("ld.global.cg.u32 %0, [%1];" : "=r"(v) : "l"(p));
        }
    }
    __syncthreads();
    __threadfence();
}

__device__ __forceinline__ float fexp(float x) {
    float r;
    asm("ex2.approx.f32 %0, %1;" : "=f"(r) : "f"(x * 1.4426950408889634f));
    return r;
}
__device__ __forceinline__ float frcp(float x) {
    float r;
    asm("rcp.approx.f32 %0, %1;" : "=f"(r) : "f"(x));
    return r;
}
__device__ __forceinline__ float fsig(float x)  { return frcp(1.0f + fexp(-x)); }
__device__ __forceinline__ float ftanh(float x) { return 1.0f - 2.0f * frcp(1.0f + fexp(2.0f * x)); }

// --------------------------- kernel ----------------------------------------
__global__ void __launch_bounds__(NTHR, 1)
stlstm_kernel(const float* __restrict__ x,
              const float* __restrict__ Wx,
              const float* __restrict__ Whs,
              const float* __restrict__ Wht,
              const float* __restrict__ bias,
              float* __restrict__ out)
{
    extern __shared__ float sm[];
    float* W_s = sm + W_OFF;    // [1280][24]: local cols 0-9 at +0, 10-19 at +12
    float* red = sm + R_OFF;
    float* c_s = sm + C_OFF;

    const int t   = threadIdx.x;
    const int cta = blockIdx.x;
    const int nt  = cta;

    // -------- pre-barrier init: flags, x transpose, ring zero, weights ------
    if (t == 0) *(volatile unsigned*)&g_flags[cta * 8] = 0u;
    {
        float* tmp = red;                      // 20736 floats >= 64*257
        for (int tj = cta; tj < STEPS; tj += NCTA) {
            const float* xsrc = x + (size_t)tj * (Bb * Ii);
            for (int idx = t; idx < Bb * Ii; idx += NTHR) {
                int bb = idx >> 8, ii = idx & 255;
                tmp[bb * 257 + ii] = xsrc[idx];
            }
            __syncthreads();
            float* xdst = g_xT + (size_t)tj * XB;
            for (int idx = t; idx < Bb * Ii; idx += NTHR) {
                int ii = idx >> 6, bb = idx & 63;
                xdst[idx] = tmp[bb * 257 + ii];
            }
            __syncthreads();
        }
    }
    {   // zero h-ring slots 7..31 (all early reads land there)
        float* z = g_hT + 7 * HB;
        for (int idx = cta * NTHR + t; idx < 25 * HB; idx += NCTA * NTHR) z[idx] = 0.0f;
    }
    for (int idx = t; idx < 25 * 256; idx += NTHR) c_s[idx] = 0.0f;

    // weights: local col c in [0,20); SMEM slot c<10 ? c : c+2
    for (int idx = t; idx < 1280 * NPC; idx += NTHR) {
        int k = idx / NPC, c = idx % NPC;
        int g = c >> 2, hc = c & 3;
        int col = g * Hh + nt * 4 + hc;
        float w;
        if (k < Hh)            w = Whs[(size_t)k * G5H + col];
        else if (k < 2 * Hh)   w = Wht[(size_t)(k - Hh) * G5H + col];
        else                   w = Wx [(size_t)(k - 2 * Hh) * G5H + col];
        W_s[k * WSTR + (c < 10 ? c : c + 2)] = w;
    }

    float ba[5];
    {
        int hc = t & 3;
        #pragma unroll
        for (int g = 0; g < 5; ++g) ba[g] = bias[g * Hh + nt * 4 + hc];
    }

    init_barrier();   // x ready, rings zeroed, flags zeroed

    // GEMM mapping: thread = (ng, mg, ks); ks warp-uniform.
    const int ng   = t & 1;
    const int mg   = (t >> 1) & 15;
    const int ks   = t >> 5;
    const int b_lo = mg * 4;
    const int ng12 = ng * 12;            // W_s half offset (floats)
    const int ng10 = ng * 10;            // red half offset
    const int khW  = ks * 64;            // W row base, h part
    const int kxW  = 1024 + ks * 16;     // W row base, x part

    const int el  = t & 255;             // reduce element (both halves)
    const int bg  = el >> 2;
    const int hcg = el & 3;

    unsigned long long acc[4][5];
    float4 bufA[4], bufB[4];

#define ZERO_ACC()                                                            \
    {  _Pragma("unroll")                                                      \
       for (int i = 0; i < 4; ++i)                                            \
           _Pragma("unroll")                                                  \
           for (int g = 0; g < 5; ++g) acc[i][g] = 0ull; }

#define LOADBLK(BUF, PA, BLK)                                                 \
    {  _Pragma("unroll")                                                      \
       for (int u = 0; u < 4; ++u)                                            \
           BUF[u] = __ldcg((const float4*)((PA) + ((BLK) * 4 + u) * 64));     \
    }

#define FMABLK(BUF, KWB, BLK)                                                 \
    {  _Pragma("unroll")                                                      \
       for (int u = 0; u < 4; ++u) {                                          \
           const float* wr = W_s + ((KWB) + (BLK) * 4 + u) * WSTR + ng12;     \
           ulonglong2 wa = *(const ulonglong2*)(wr);                          \
           ulonglong2 wb = *(const ulonglong2*)(wr + 4);                      \
           unsigned long long w4 = *(const unsigned long long*)(wr + 8);      \
           float av[4] = {BUF[u].x, BUF[u].y, BUF[u].z, BUF[u].w};            \
           _Pragma("unroll")                                                  \
           for (int i = 0; i < 4; ++i) {                                      \
               unsigned long long aa;                                         \
               asm("mov.b64 %0, {%1, %1};" : "=l"(aa) : "f"(av[i]));          \
               asm("fma.rn.f32x2 %0, %1, %2, %0;" : "+l"(acc[i][0]) : "l"(aa), "l"(wa.x)); \
               asm("fma.rn.f32x2 %0, %1, %2, %0;" : "+l"(acc[i][1]) : "l"(aa), "l"(wa.y)); \
               asm("fma.rn.f32x2 %0, %1, %2, %0;" : "+l"(acc[i][2]) : "l"(aa), "l"(wb.x)); \
               asm("fma.rn.f32x2 %0, %1, %2, %0;" : "+l"(acc[i][3]) : "l"(aa), "l"(wb.y)); \
               asm("fma.rn.f32x2 %0, %1, %2, %0;" : "+l"(acc[i][4]) : "l"(aa), "l"(w4)); \
           } } }

    // full x-part (16 rows, 4 blocks) — runs under the grid barrier
#define XGEMM(S)                                                              \
    {  const float* pX = g_xT + (size_t)(S) * XB + (ks * 16) * 64 + b_lo;     \
       LOADBLK(bufA, pX, 0)                                                   \
       LOADBLK(bufB, pX, 1)                                                   \
       FMABLK(bufA, kxW, 0)                                                   \
       LOADBLK(bufA, pX, 2)                                                   \
       FMABLK(bufB, kxW, 1)                                                   \
       LOADBLK(bufB, pX, 3)                                                   \
       FMABLK(bufA, kxW, 2)                                                   \
       FMABLK(bufB, kxW, 3) }

    // prologue: x-part of step 0
    ZERO_ACC()
    XGEMM(0)

    // ---------------- main sequential loop ----------------------------------
    for (int step = 0; step < STEPS; ++step) {

        // ---- h-part GEMM: 16 uniform blocks ----
        {
            const float* h1  = g_hT + ((step - 1)  & 31) * HB;
            const float* h25 = g_hT + ((step - 25) & 31) * HB;
            const float* pH  = ((ks < 8) ? (h1 + khW * 64)
                                         : (h25 + (khW - 512) * 64)) + b_lo;
            LOADBLK(bufA, pH, 0)
            #pragma unroll 1
            for (int blk = 0; blk < 16; blk += 2) {
                LOADBLK(bufB, pH, blk + 1)
                FMABLK(bufA, khW, blk)
                if (blk + 2 < 16) LOADBLK(bufA, pH, blk + 2)
                FMABLK(bufB, khW, blk + 1)
            }
        }

        __syncthreads();   // red buffer free (previous gate phase done)

        // ---- store partials: thread's 10 contiguous local cols ----
        {
            float* rrow = red + ks * RS + ng10;
            #pragma unroll
            for (int i = 0; i < 4; ++i) {
                float* rb = rrow + (b_lo + i) * NPC;
                #pragma unroll
                for (int p = 0; p < 5; ++p)
                    *(float2*)(rb + 2 * p) = *(float2*)&acc[i][p];
            }
        }
        __syncthreads();

        // ---- stage 1: upper half folds rows 7..15 into row 7 ----
        if (t >= 256) {
            #pragma unroll
            for (int g = 0; g < 5; ++g) {
                float* rp = red + bg * NPC + g * 4 + hcg;
                float s = rp[7 * RS];
                #pragma unroll
                for (int q = 8; q < KSL; ++q) s += rp[q * RS];
                rp[7 * RS] = s;
            }
        }
        __syncthreads();

        // ---- stage 2: lower half sums rows 0..7 + gates ----
        if (t < 256) {
            float z[5];
            #pragma unroll
            for (int g = 0; g < 5; ++g) {
                float s = ba[g];
                const float* rp = red + bg * NPC + g * 4 + hcg;
                #pragma unroll
                for (int q = 0; q < 8; ++q) s += rp[q * RS];
                z[g] = s;
            }
            float cs = c_s[((step + 24) % 25) * 256 + t];
            float ct = c_s[(step % 25) * 256 + t];
            float cc = fsig(z[0]) * ftanh(z[3]) + fsig(z[1]) * cs + fsig(z[2]) * ct;
            float hv = fsig(z[4]) * ftanh(cc);
            c_s[(step % 25) * 256 + t] = cc;

            int n = nt * 4 + hcg;
            g_hT[(step & 31) * HB + n * 64 + bg] = hv;
            out[(size_t)step * BH + bg * Hh + n] = hv;
        }

        // ---- arrive, hide barrier behind next step's full x-part ----
        bar_arrive(cta, t, (unsigned)(step + 1));
        if (step + 1 < STEPS) {
            ZERO_ACC()
            XGEMM(step + 1)
            bar_wait(t, (unsigned)(step + 1));
        }
    }
#undef ZERO_ACC
#undef LOADBLK
#undef FMABLK
#undef XGEMM
}

// --------------------------- launch ----------------------------------------
extern "C" void kernel_launch(void* const* d_in, const int* in_sizes, int n_in,
                              void* d_out, int out_size)
{
    const float* x    = (const float*)d_in[0];
    const float* Wx   = (const float*)d_in[1];
    const float* Whs  = (const float*)d_in[2];
    const float* Wht  = (const float*)d_in[3];
    const float* bias = (const float*)d_in[4];
    float*       out  = (float*)d_out;

    cudaFuncSetAttribute(stlstm_kernel,
                         cudaFuncAttributeMaxDynamicSharedMemorySize, SMEM_BYTES);
    stlstm_kernel<<<NCTA, NTHR, SMEM_BYTES>>>(x, Wx, Whs, Wht, bias, out);
}